// round 16
// baseline (speedup 1.0000x reference)
#include <cuda_runtime.h>

// ---------------------------------------------------------------------------
// Photonic mesh simulation, N=128 -- SINGLE-KERNEL version.
// Best-measured mesh structure (R5/R15, 27.1us): one warp per column, lane t
// owns rows 8t..8t+7 in registers, scalar FFMA, distance-2 double-buffered
// slots. ROUND 16: the phase table + phase kernel are ELIMINATED -- each body
// loads raw theta (float4, half the bytes) and computes the 8 phases with
// __sincosf (MUFU pipe, overlapped with FMA). One kernel in the graph.
// Output serialization identical to rounds 4-15 (mode on out_size).
// ---------------------------------------------------------------------------

#define NCOLS   128
#define FULL    0xffffffffu

#define AM_  0.97467943448089633f    // sqrt(1-0.05)
#define PP_  0.71063352017759484f    // sqrt(0.5+0.005)
#define QQ_  0.70356236397351441f    // sqrt(0.5-0.005)
#define AMP_ (AM_*PP_)
#define AMQ_ (AM_*QQ_)
#define AX_  0.98994949366116653f    // sqrt(1-0.02)
#define XC_  (AX_*0.1f)                       // aX*sqrt(CT)
#define XS_  (AX_*0.99498743710661995f)       // aX*sqrt(1-CT), corner scalar

// v *= (c + i s)
#define CMUL(v, c_, s_) do { \
    float _nx = fmaf((v).x, (c_), -(v).y * (s_)); \
    float _ny = fmaf((v).x, (s_),  (v).y * (c_)); \
    (v).x = _nx; (v).y = _ny; } while (0)

// [a;b] <- [[A, iB],[iB, A]] [a;b]
#define MIX(a, b, A, B) do { \
    float _ar = fmaf((A), (a).x, -(B) * (b).y); \
    float _ai = fmaf((A), (a).y,  (B) * (b).x); \
    float _br = fmaf((A), (b).x, -(B) * (a).y); \
    float _bi = fmaf((A), (b).y,  (B) * (a).x); \
    (a).x = _ar; (a).y = _ai; (b).x = _br; (b).y = _bi; } while (0)

// D from slot S: S[0..3] = (c,s) for layer a ports 4t..4t+3 -> v0,v2,v4,v6
#define APPLY_DA(S) do { \
    CMUL(v0, (S)[0].x, (S)[0].y); \
    CMUL(v2, (S)[1].x, (S)[1].y); \
    CMUL(v4, (S)[2].x, (S)[2].y); \
    CMUL(v6, (S)[3].x, (S)[3].y); } while (0)
#define APPLY_DB(S) do { \
    CMUL(v0, (S)[4].x, (S)[4].y); \
    CMUL(v2, (S)[5].x, (S)[5].y); \
    CMUL(v4, (S)[6].x, (S)[6].y); \
    CMUL(v6, (S)[7].x, (S)[7].y); } while (0)

#define APPLY_M() do { \
    MIX(v0, v1, AMP_, AMQ_); \
    MIX(v2, v3, AMP_, AMQ_); \
    MIX(v4, v5, AMP_, AMQ_); \
    MIX(v6, v7, AMP_, AMQ_); } while (0)

#define APPLY_X() do { \
    float _nb0x = __shfl_down_sync(FULL, v0.x, 1); /* lane t+1's v0 = row 8t+8 */ \
    float _nb0y = __shfl_down_sync(FULL, v0.y, 1); \
    float _nb7x = __shfl_up_sync  (FULL, v7.x, 1); /* lane t-1's v7 = row 8t-1 */ \
    float _nb7y = __shfl_up_sync  (FULL, v7.y, 1); \
    MIX(v1, v2, XC_, XS_); \
    MIX(v3, v4, XC_, XS_); \
    MIX(v5, v6, XC_, XS_); \
    float _n7x = fmaf(XC_, v7.x, -XS_ * _nb0y); \
    float _n7y = fmaf(XC_, v7.y,  XS_ * _nb0x); \
    float _n0x = fmaf(XC_, v0.x, -XS_ * _nb7y); \
    float _n0y = fmaf(XC_, v0.y,  XS_ * _nb7x); \
    v7.x = (t < 31) ? _n7x : XS_ * v7.x;   /* row 255 corner */ \
    v7.y = (t < 31) ? _n7y : XS_ * v7.y; \
    v0.x = (t > 0)  ? _n0x : XS_ * v0.x;   /* row 0 corner */ \
    v0.y = (t > 0)  ? _n0y : XS_ * v0.y; } while (0)

// load theta for iteration jn (layers 2jn+1, 2jn+2, ports 4t..4t+3) and
// compute the 8 phases into slot S (float2[8]) via fast sincos (MUFU pipe)
#define COMPUTE(S, jn) do { \
    float4 _ta = *reinterpret_cast<const float4*>(th_ev + (2 * (jn) + 1) * NCOLS + 4 * t); \
    float4 _tb = *reinterpret_cast<const float4*>(th_ev + (2 * (jn) + 2) * NCOLS + 4 * t); \
    __sincosf(_ta.x, &(S)[0].y, &(S)[0].x); \
    __sincosf(_ta.y, &(S)[1].y, &(S)[1].x); \
    __sincosf(_ta.z, &(S)[2].y, &(S)[2].x); \
    __sincosf(_ta.w, &(S)[3].y, &(S)[3].x); \
    __sincosf(_tb.x, &(S)[4].y, &(S)[4].x); \
    __sincosf(_tb.y, &(S)[5].y, &(S)[5].x); \
    __sincosf(_tb.z, &(S)[6].y, &(S)[6].x); \
    __sincosf(_tb.w, &(S)[7].y, &(S)[7].x); } while (0)

__global__ void __launch_bounds__(32, 1)
mesh_kernel(const float* __restrict__ theta_in,
            const float* __restrict__ th_ev,     // theta_even (255,128)
            const float* __restrict__ theta_out,
            float* __restrict__ out,
            int mode)   // 1 = real-only (16384 floats), 2 = planar (32768 floats)
{
    const int c = blockIdx.x;    // column (input port)
    const int t = threadIdx.x;   // lane: rows 8t..8t+7

    float2 v0 = {0.f, 0.f}, v1 = {0.f, 0.f}, v2 = {0.f, 0.f}, v3 = {0.f, 0.f};
    float2 v4 = {0.f, 0.f}, v5 = {0.f, 0.f}, v6 = {0.f, 0.f}, v7 = {0.f, 0.f};

    // --- input: rows 2c, 2c+1 of column c of MMI_IN @ diag(e^{i th_in}) ---
    {
        float s, co;
        sincosf(theta_in[c], &s, &co);
        float2 ain = make_float2( AMP_ * co, AMP_ * s);   //  aM*p * e^{i th}
        float2 bin = make_float2(-AMQ_ * s,  AMQ_ * co);  // i*aM*q * e^{i th}
        int slot = 2 * c - 8 * t;   // even slot 0/2/4/6 if rows in this lane
        if      (slot == 0) { v0 = ain; v1 = bin; }
        else if (slot == 2) { v2 = ain; v3 = bin; }
        else if (slot == 4) { v4 = ain; v5 = bin; }
        else if (slot == 6) { v6 = ain; v7 = bin; }
    }

    // --- D0, M, X (layer-0 phases computed inline) ---
    {
        float4 t0 = *reinterpret_cast<const float4*>(th_ev + 4 * t);
        float2 p0, p1, p2, p3;
        __sincosf(t0.x, &p0.y, &p0.x);
        __sincosf(t0.y, &p1.y, &p1.x);
        __sincosf(t0.z, &p2.y, &p2.x);
        __sincosf(t0.w, &p3.y, &p3.x);
        CMUL(v0, p0.x, p0.y);
        CMUL(v2, p1.x, p1.y);
        CMUL(v4, p2.x, p2.y);
        CMUL(v6, p3.x, p3.y);
        APPLY_M();
        APPLY_X();
    }

    // Virtual iteration j (0..126) consumes layers 2j+1 (a), 2j+2 (b).
    // j = 0..125: D,M,D,M,X.  j = 126: tail D253, M, D254.
    // Distance-2 double-buffered phase slots, recomputed at end of each body.
    float2 S0[8], S1[8];
    COMPUTE(S0, 0);
    COMPUTE(S1, 1);

#pragma unroll 1
    for (int j = 0; j < 126; j += 2) {
        {   // iteration j: uses slot 0, recomputes j+2 into slot 0
            APPLY_DA(S0);
            APPLY_M();
            APPLY_DB(S0);
            APPLY_M();
            APPLY_X();
            int jn = (j + 2 <= 126) ? (j + 2) : 126;     // clamp (redundant ok)
            COMPUTE(S0, jn);
        }
        {   // iteration j+1: uses slot 1, recomputes j+3 into slot 1
            APPLY_DA(S1);
            APPLY_M();
            APPLY_DB(S1);
            APPLY_M();
            APPLY_X();
            int jn = (j + 3 <= 126) ? (j + 3) : 126;
            COMPUTE(S1, jn);
        }
    }

    // --- tail j=126: D253, M, D254 (slot 0 last computed with jn=126) ---
    APPLY_DA(S0);
    APPLY_M();
    APPLY_DB(S0);

    // --- output rows jj = 4t..4t+3: MMI_OUT pair reduce, then e^{i th_out} ---
#define OUTP(va, vb, jj) do { \
        float _ox = fmaf(AMP_, (va).x, -AMQ_ * (vb).y); \
        float _oy = fmaf(AMP_, (va).y,  AMQ_ * (vb).x); \
        float _so, _co; sincosf(theta_out[jj], &_so, &_co); \
        float _re = _ox * _co - _oy * _so; \
        float _im = _ox * _so + _oy * _co; \
        if (mode == 1) { out[(jj) * NCOLS + c] = _re; } \
        else { out[(jj) * NCOLS + c] = _re; \
               out[NCOLS * NCOLS + (jj) * NCOLS + c] = _im; } } while (0)

    OUTP(v0, v1, 4 * t);
    OUTP(v2, v3, 4 * t + 1);
    OUTP(v4, v5, 4 * t + 2);
    OUTP(v6, v7, 4 * t + 3);
#undef OUTP
}

extern "C" void kernel_launch(void* const* d_in, const int* in_sizes, int n_in,
                              void* d_out, int out_size) {
    // Inputs identified by SIZE (theta_even = unique 32640-elem array;
    // theta_in precedes theta_out in both dict and alphabetical order).
    const float* th_ev  = nullptr;
    const float* small_[2] = {nullptr, nullptr};
    int ns = 0;
    for (int i = 0; i < n_in && i < 3; i++) {
        if (in_sizes[i] > 1000) th_ev = (const float*)d_in[i];
        else if (ns < 2)        small_[ns++] = (const float*)d_in[i];
    }
    const float* th_in  = small_[0];
    const float* th_out = small_[1];

    int mode = (out_size == NCOLS * NCOLS) ? 1 : 2;  // 16384 -> real-only, else planar

    mesh_kernel<<<NCOLS, 32>>>(th_in, th_ev, th_out, (float*)d_out, mode);
}

// round 17
// speedup vs baseline: 1.1400x; 1.1400x over previous
#include <cuda_runtime.h>

// ---------------------------------------------------------------------------
// Photonic mesh simulation, N=128. FINAL (round-15 measured optimum, 27.1us):
// one warp per column, lane t owns rows 8t..8t+7 in registers, scalar FFMA,
// float2 phase table precomputed by a tiny phase kernel (__sincosf fast path),
// distance-2 double-buffered slot prefetch. Output mode branches on out_size.
//
// Session design-space map (all falsified alternatives):
//   smem-barrier/layer 36.9 | f32x2 packed 36.0 | fused fp-table 39.0 |
//   2-warp split 47.1 | hoist+rotation ~28.7 | explicit PF 30.6 |
//   depth-halving 2-chain 35.5 | G-fusion 55.2 | in-kernel sincos 31.3
// ---------------------------------------------------------------------------

#define NCOLS   128
#define NLAYERS 255
#define FULL    0xffffffffu

#define AM_  0.97467943448089633f    // sqrt(1-0.05)
#define PP_  0.71063352017759484f    // sqrt(0.5+0.005)
#define QQ_  0.70356236397351441f    // sqrt(0.5-0.005)
#define AMP_ (AM_*PP_)
#define AMQ_ (AM_*QQ_)
#define AX_  0.98994949366116653f    // sqrt(1-0.02)
#define XC_  (AX_*0.1f)                       // aX*sqrt(CT)
#define XS_  (AX_*0.99498743710661995f)       // aX*sqrt(1-CT), corner scalar

// phase table: layer k, lane t reads float4s [k*64 + 2t] and [k*64 + 2t + 1]
// (= phases for theta_even ports 4t..4t+3, stored as (cos,sin) float2 pairs)
__device__ float4 g_phase4[NLAYERS * 64];

__global__ void phase_kernel(const float* __restrict__ theta_even) {
    int i = blockIdx.x * blockDim.x + threadIdx.x;
    if (i < NLAYERS * NCOLS) {
        float s, c;
        __sincosf(theta_even[i], &s, &c);   // fast path; inputs in [0, 2pi)
        reinterpret_cast<float2*>(g_phase4)[i] = make_float2(c, s);
    }
}

// v *= (c + i s)
#define CMUL(v, c_, s_) do { \
    float _nx = fmaf((v).x, (c_), -(v).y * (s_)); \
    float _ny = fmaf((v).x, (s_),  (v).y * (c_)); \
    (v).x = _nx; (v).y = _ny; } while (0)

// [a;b] <- [[A, iB],[iB, A]] [a;b]
#define MIX(a, b, A, B) do { \
    float _ar = fmaf((A), (a).x, -(B) * (b).y); \
    float _ai = fmaf((A), (a).y,  (B) * (b).x); \
    float _br = fmaf((A), (b).x, -(B) * (a).y); \
    float _bi = fmaf((A), (b).y,  (B) * (a).x); \
    (a).x = _ar; (a).y = _ai; (b).x = _br; (b).y = _bi; } while (0)

#define APPLY_D(p01, p23) do { \
    CMUL(v0, (p01).x, (p01).y); \
    CMUL(v2, (p01).z, (p01).w); \
    CMUL(v4, (p23).x, (p23).y); \
    CMUL(v6, (p23).z, (p23).w); } while (0)

#define APPLY_M() do { \
    MIX(v0, v1, AMP_, AMQ_); \
    MIX(v2, v3, AMP_, AMQ_); \
    MIX(v4, v5, AMP_, AMQ_); \
    MIX(v6, v7, AMP_, AMQ_); } while (0)

#define APPLY_X() do { \
    float _nb0x = __shfl_down_sync(FULL, v0.x, 1); /* lane t+1's v0 = row 8t+8 */ \
    float _nb0y = __shfl_down_sync(FULL, v0.y, 1); \
    float _nb7x = __shfl_up_sync  (FULL, v7.x, 1); /* lane t-1's v7 = row 8t-1 */ \
    float _nb7y = __shfl_up_sync  (FULL, v7.y, 1); \
    MIX(v1, v2, XC_, XS_); \
    MIX(v3, v4, XC_, XS_); \
    MIX(v5, v6, XC_, XS_); \
    float _n7x = fmaf(XC_, v7.x, -XS_ * _nb0y); \
    float _n7y = fmaf(XC_, v7.y,  XS_ * _nb0x); \
    float _n0x = fmaf(XC_, v0.x, -XS_ * _nb7y); \
    float _n0y = fmaf(XC_, v0.y,  XS_ * _nb7x); \
    v7.x = (t < 31) ? _n7x : XS_ * v7.x;   /* row 255 corner */ \
    v7.y = (t < 31) ? _n7y : XS_ * v7.y; \
    v0.x = (t > 0)  ? _n0x : XS_ * v0.x;   /* row 0 corner */ \
    v0.y = (t > 0)  ? _n0y : XS_ * v0.y; } while (0)

#define PH(k, h) g_phase4[(k) * 64 + 2 * t + (h)]

__global__ void __launch_bounds__(32, 1)
mesh_kernel(const float* __restrict__ theta_in,
            const float* __restrict__ theta_out,
            float* __restrict__ out,
            int mode)   // 1 = real-only (16384 floats), 2 = planar (32768 floats)
{
    const int c = blockIdx.x;    // column (input port)
    const int t = threadIdx.x;   // lane: rows 8t..8t+7

    float2 v0 = {0.f, 0.f}, v1 = {0.f, 0.f}, v2 = {0.f, 0.f}, v3 = {0.f, 0.f};
    float2 v4 = {0.f, 0.f}, v5 = {0.f, 0.f}, v6 = {0.f, 0.f}, v7 = {0.f, 0.f};

    // --- input: rows 2c, 2c+1 of column c of MMI_IN @ diag(e^{i th_in}) ---
    {
        float s, co;
        sincosf(theta_in[c], &s, &co);
        float2 ain = make_float2( AMP_ * co, AMP_ * s);   //  aM*p * e^{i th}
        float2 bin = make_float2(-AMQ_ * s,  AMQ_ * co);  // i*aM*q * e^{i th}
        int slot = 2 * c - 8 * t;   // even slot 0/2/4/6 if rows in this lane
        if      (slot == 0) { v0 = ain; v1 = bin; }
        else if (slot == 2) { v2 = ain; v3 = bin; }
        else if (slot == 4) { v4 = ain; v5 = bin; }
        else if (slot == 6) { v6 = ain; v7 = bin; }
    }

    // --- D0, M, X ---
    {
        float4 p01 = PH(0, 0), p23 = PH(0, 1);
        APPLY_D(p01, p23);
        APPLY_M();
        APPLY_X();
    }

    // Virtual iteration j (0..126) consumes layers 2j+1 (a) and 2j+2 (b).
    // j = 0..125: D,M,D,M,X.  j = 126: tail D253, M, D254.
    // Distance-2 double-buffered prefetch; unroll-2 keeps slots in registers.
    float4 s0a0 = PH(1, 0), s0a1 = PH(1, 1), s0b0 = PH(2, 0), s0b1 = PH(2, 1);
    float4 s1a0 = PH(3, 0), s1a1 = PH(3, 1), s1b0 = PH(4, 0), s1b1 = PH(4, 1);

#pragma unroll 1
    for (int j = 0; j < 126; j += 2) {
        {   // iteration j: uses slot 0, prefetches j+2 into slot 0
            int jn = (j + 2 <= 126) ? (j + 2) : 126;     // clamp (redundant load ok)
            float4 na0 = PH(2 * jn + 1, 0), na1 = PH(2 * jn + 1, 1);
            float4 nb0 = PH(2 * jn + 2, 0), nb1 = PH(2 * jn + 2, 1);
            APPLY_D(s0a0, s0a1);
            APPLY_M();
            APPLY_D(s0b0, s0b1);
            APPLY_M();
            APPLY_X();
            s0a0 = na0; s0a1 = na1; s0b0 = nb0; s0b1 = nb1;
        }
        {   // iteration j+1: uses slot 1, prefetches j+3 into slot 1
            int jn = (j + 3 <= 126) ? (j + 3) : 126;
            float4 na0 = PH(2 * jn + 1, 0), na1 = PH(2 * jn + 1, 1);
            float4 nb0 = PH(2 * jn + 2, 0), nb1 = PH(2 * jn + 2, 1);
            APPLY_D(s1a0, s1a1);
            APPLY_M();
            APPLY_D(s1b0, s1b1);
            APPLY_M();
            APPLY_X();
            s1a0 = na0; s1a1 = na1; s1b0 = nb0; s1b1 = nb1;
        }
    }

    // --- tail j=126: D253, M, D254 (slot 0 holds layers 253/254) ---
    APPLY_D(s0a0, s0a1);
    APPLY_M();
    CMUL(v0, s0b0.x, s0b0.y);
    CMUL(v2, s0b0.z, s0b0.w);
    CMUL(v4, s0b1.x, s0b1.y);
    CMUL(v6, s0b1.z, s0b1.w);

    // --- output rows jj = 4t..4t+3: MMI_OUT pair reduce, then e^{i th_out} ---
#define OUTP(va, vb, jj) do { \
        float _ox = fmaf(AMP_, (va).x, -AMQ_ * (vb).y); \
        float _oy = fmaf(AMP_, (va).y,  AMQ_ * (vb).x); \
        float _so, _co; sincosf(theta_out[jj], &_so, &_co); \
        float _re = _ox * _co - _oy * _so; \
        float _im = _ox * _so + _oy * _co; \
        if (mode == 1) { out[(jj) * NCOLS + c] = _re; } \
        else { out[(jj) * NCOLS + c] = _re; \
               out[NCOLS * NCOLS + (jj) * NCOLS + c] = _im; } } while (0)

    OUTP(v0, v1, 4 * t);
    OUTP(v2, v3, 4 * t + 1);
    OUTP(v4, v5, 4 * t + 2);
    OUTP(v6, v7, 4 * t + 3);
#undef OUTP
}

extern "C" void kernel_launch(void* const* d_in, const int* in_sizes, int n_in,
                              void* d_out, int out_size) {
    // Inputs identified by SIZE (theta_even = unique 32640-elem array;
    // theta_in precedes theta_out in both dict and alphabetical order).
    const float* th_ev  = nullptr;
    const float* small_[2] = {nullptr, nullptr};
    int ns = 0;
    for (int i = 0; i < n_in && i < 3; i++) {
        if (in_sizes[i] > 1000) th_ev = (const float*)d_in[i];
        else if (ns < 2)        small_[ns++] = (const float*)d_in[i];
    }
    const float* th_in  = small_[0];
    const float* th_out = small_[1];

    int mode = (out_size == NCOLS * NCOLS) ? 1 : 2;  // 16384 -> real-only, else planar

    phase_kernel<<<(NLAYERS * NCOLS + 255) / 256, 256>>>(th_ev);
    mesh_kernel<<<NCOLS, 32>>>(th_in, th_out, (float*)d_out, mode);
}